// round 4
// baseline (speedup 1.0000x reference)
#include <cuda_runtime.h>

typedef unsigned long long u64;

#define LSEQ    2048
#define DIM     32
#define NLDX    2047          // number of dx terms
#define CL      5             // consecutive l's per lane (odd -> conflict-free with stride 36)
#define CHUNK   160           // CL * 32
#define SROWS   161           // CHUNK + 1 boundary row
#define SSTRIDE 36            // floats per row in smem (16B aligned, bank shift 4/row)
#define NWARPS  10
#define NTHREADS 320
#define HALFL   1024
#define NCHUNK  7             // ceil(1024/160)
#define OUTD    528

__constant__ int c_i0[NWARPS] = {0,0,0,0, 8,8,8, 16,16, 24};
__constant__ int c_j0[NWARPS] = {0,8,16,24, 8,16,24, 16,24, 24};

__device__ __forceinline__ u64 pk2(float lo, float hi) {
    u64 r; asm("mov.b64 %0, {%1, %2};" : "=l"(r) : "f"(lo), "f"(hi)); return r;
}
__device__ __forceinline__ void upk2(u64 v, float& a, float& b) {
    asm("mov.b64 {%0, %1}, %2;" : "=f"(a), "=f"(b) : "l"(v));
}
__device__ __forceinline__ u64 fma2(u64 a, u64 b, u64 c) {
    u64 r; asm("fma.rn.f32x2 %0, %1, %2, %3;" : "=l"(r) : "l"(a), "l"(b), "l"(c)); return r;
}
__device__ __forceinline__ u64 add2(u64 a, u64 b) {
    u64 r; asm("add.rn.f32x2 %0, %1, %2;" : "=l"(r) : "l"(a), "l"(b)); return r;
}

__global__ void zero_out_kernel(float* __restrict__ out, int n) {
    int i = blockIdx.x * blockDim.x + threadIdx.x;
    if (i < n) out[i] = 0.0f;
}

__global__ __launch_bounds__(NTHREADS, 1)
void logsig_main(const float* __restrict__ x, float* __restrict__ out)
{
    __shared__ __align__(16) float sbuf[2][SROWS * SSTRIDE];
    __shared__ float sx0[DIM];
    __shared__ float sxL[DIM];

    const int b    = blockIdx.x >> 1;
    const int half = blockIdx.x & 1;
    const int tid  = threadIdx.x;
    const int wid  = tid >> 5;
    const int lane = tid & 31;

    const float* __restrict__ xb = x + (size_t)b * (LSEQ * DIM);

    if (tid < DIM)            sx0[tid]       = xb[tid];
    else if (tid < 2 * DIM)   sxL[tid - DIM] = xb[(size_t)(LSEQ - 1) * DIM + (tid - DIM)];

    const int lo = half * HALFL;
    const int hi = (half == 0) ? HALFL : NLDX;

    const int i0 = c_i0[wid];
    const int j0 = c_j0[wid];

    u64 acc[8][4];
#pragma unroll
    for (int a = 0; a < 8; a++)
#pragma unroll
        for (int q = 0; q < 4; q++) acc[a][q] = 0ull;

    // stage chunk 0
    {
        const int base = lo;
        for (int e = tid; e < SROWS * 8; e += NTHREADS) {
            int r  = e >> 3;
            int c4 = (e & 7) << 2;
            int gr = base + r;
            if (gr < LSEQ) {
                float4 v = *reinterpret_cast<const float4*>(xb + (size_t)gr * DIM + c4);
                *reinterpret_cast<float4*>(&sbuf[0][r * SSTRIDE + c4]) = v;
            }
        }
    }
    __syncthreads();

    for (int c = 0; c < NCHUNK; c++) {
        // prefetch next chunk into the other buffer (overlaps with compute below)
        if (c + 1 < NCHUNK) {
            const int base = lo + (c + 1) * CHUNK;
            float* dst = sbuf[(c + 1) & 1];
            for (int e = tid; e < SROWS * 8; e += NTHREADS) {
                int r  = e >> 3;
                int c4 = (e & 7) << 2;
                int gr = base + r;
                if (gr < LSEQ) {
                    float4 v = *reinterpret_cast<const float4*>(xb + (size_t)gr * DIM + c4);
                    *reinterpret_cast<float4*>(&dst[r * SSTRIDE + c4]) = v;
                }
            }
        }

        const float* buf = sbuf[c & 1];
        const int l0l = lo + c * CHUNK + lane * CL;   // first l of this lane's run
        const int r0  = lane * CL;

        // load current row (l) registers
        const float* rowc = buf + r0 * SSTRIDE;
        float4 a0 = *reinterpret_cast<const float4*>(rowc + i0);
        float4 a1 = *reinterpret_cast<const float4*>(rowc + i0 + 4);
        float4 b0 = *reinterpret_cast<const float4*>(rowc + j0);
        float4 b1 = *reinterpret_cast<const float4*>(rowc + j0 + 4);
        float ci[8] = {a0.x,a0.y,a0.z,a0.w, a1.x,a1.y,a1.z,a1.w};
        float cj[8] = {b0.x,b0.y,b0.z,b0.w, b1.x,b1.y,b1.z,b1.w};

#pragma unroll
        for (int t = 0; t < CL; t++) {
            const float* rown = buf + (r0 + t + 1) * SSTRIDE;
            float4 n0 = *reinterpret_cast<const float4*>(rown + i0);
            float4 n1 = *reinterpret_cast<const float4*>(rown + i0 + 4);
            float4 m0 = *reinterpret_cast<const float4*>(rown + j0);
            float4 m1 = *reinterpret_cast<const float4*>(rown + j0 + 4);
            float ni[8] = {n0.x,n0.y,n0.z,n0.w, n1.x,n1.y,n1.z,n1.w};
            float nj[8] = {m0.x,m0.y,m0.z,m0.w, m1.x,m1.y,m1.z,m1.w};

            if (l0l + t < hi) {
                // d pairs along j
                float d[8];
#pragma unroll
                for (int k = 0; k < 8; k++) d[k] = nj[k] - cj[k];
                u64 d2[4];
#pragma unroll
                for (int q = 0; q < 4; q++) d2[q] = pk2(d[2*q], d[2*q+1]);
                // s duplicated along i
                u64 sd[8];
#pragma unroll
                for (int a = 0; a < 8; a++) {
                    float s = ci[a] + ni[a];
                    sd[a] = pk2(s, s);
                }
#pragma unroll
                for (int a = 0; a < 8; a++)
#pragma unroll
                    for (int q = 0; q < 4; q++)
                        acc[a][q] = fma2(sd[a], d2[q], acc[a][q]);
                // rotate: next becomes current
#pragma unroll
                for (int k = 0; k < 8; k++) { ci[k] = ni[k]; cj[k] = nj[k]; }
            }
        }
        __syncthreads();
    }

    // warp-level butterfly reduction over the 32 l-slices
#pragma unroll
    for (int a = 0; a < 8; a++)
#pragma unroll
        for (int q = 0; q < 4; q++) {
            u64 v = acc[a][q];
#pragma unroll
            for (int off = 16; off > 0; off >>= 1)
                v = add2(v, __shfl_xor_sync(0xFFFFFFFFu, v, off));
            acc[a][q] = v;
        }

    float* outb = out + (size_t)b * OUTD;

    // level-1 terms (only one block writes them; out is pre-zeroed, plain store OK)
    if (half == 0 && wid == 0) outb[lane] = sxL[lane] - sx0[lane];

    // areas: each lane writes 2 of the 64 tile entries (upper-triangle only)
#pragma unroll
    for (int e2 = 0; e2 < 2; e2++) {
        int e  = lane + 32 * e2;
        int a  = e >> 3;
        int bb = e & 7;
        int i  = i0 + a;
        int j  = j0 + bb;
        if (j > i) {
            float v0, v1; upk2(acc[a][bb >> 1], v0, v1);
            float C   = (bb & 1) ? v1 : v0;
            float val = 0.5f * C;
            if (half == 0) {
                float x0i = sx0[i];
                float li  = sxL[i] - x0i;
                float lj  = sxL[j] - sx0[j];
                val -= x0i * lj + 0.5f * li * lj;   // telescope + x0 corrections
            }
            int idx = DIM + i * (2 * DIM - 1 - i) / 2 + (j - i - 1);
            atomicAdd(&outb[idx], val);
        }
    }
}

extern "C" void kernel_launch(void* const* d_in, const int* in_sizes, int n_in,
                              void* d_out, int out_size)
{
    const float* x = (const float*)d_in[0];
    float* out = (float*)d_out;
    const int B = in_sizes[0] / (LSEQ * DIM);

    zero_out_kernel<<<(out_size + 255) / 256, 256>>>(out, out_size);
    logsig_main<<<2 * B, NTHREADS>>>(x, out);
}

// round 6
// speedup vs baseline: 3.1268x; 3.1268x over previous
#include <cuda_runtime.h>

typedef unsigned long long u64;

#define LSEQ    2048
#define DIM     32
#define CL      5             // consecutive l's per lane (odd -> conflict-free with stride 36)
#define CHUNK   160           // CL * 32
#define SROWS   161           // CHUNK + 1 boundary row
#define SSTRIDE 36            // floats per row in smem (16B aligned, bank shift 4/row)
#define NTILES  10
#define NWARPS  5             // warps per block (one tileset = 5 tiles)
#define NTHREADS 160
#define HALFL   1024
#define NCHUNK  7             // ceil(1024/160)
#define OUTD    528

__constant__ int c_i0[NTILES] = {0,0,0,0,8, 8,8,16,16,24};
__constant__ int c_j0[NTILES] = {0,8,16,24,8, 16,24,16,24,24};

__device__ __forceinline__ u64 pk2(float lo, float hi) {
    u64 r; asm("mov.b64 %0, {%1, %2};" : "=l"(r) : "f"(lo), "f"(hi)); return r;
}
__device__ __forceinline__ void upk2(u64 v, float& a, float& b) {
    asm("mov.b64 {%0, %1}, %2;" : "=f"(a), "=f"(b) : "l"(v));
}
__device__ __forceinline__ u64 fma2(u64 a, u64 b, u64 c) {
    u64 r; asm("fma.rn.f32x2 %0, %1, %2, %3;" : "=l"(r) : "l"(a), "l"(b), "l"(c)); return r;
}
__device__ __forceinline__ u64 add2(u64 a, u64 b) {
    u64 r; asm("add.rn.f32x2 %0, %1, %2;" : "=l"(r) : "l"(a), "l"(b)); return r;
}

__device__ __forceinline__ void load8(float (&v)[8], const float* p) {
    float4 a = *reinterpret_cast<const float4*>(p);
    float4 b = *reinterpret_cast<const float4*>(p + 4);
    v[0]=a.x; v[1]=a.y; v[2]=a.z; v[3]=a.w;
    v[4]=b.x; v[5]=b.y; v[6]=b.z; v[7]=b.w;
}

__global__ void zero_out_kernel(float* __restrict__ out, int n) {
    int i = blockIdx.x * blockDim.x + threadIdx.x;
    if (i < n) out[i] = 0.0f;
}

// Inner chunk compute. FULL=true -> every l in range (no masking needed).
template<bool FULL>
__device__ __forceinline__ void chunk_compute(
    const float* __restrict__ buf, int r0, int l0l, int hi,
    int i0, int j0, u64 (&acc)[8][4])
{
    const float* rowc = buf + r0 * SSTRIDE;
    float ci[8], cj[8];
    load8(ci, rowc + i0);
    load8(cj, rowc + j0);

#pragma unroll
    for (int t = 0; t < CL; t++) {
        const float* rown = buf + (r0 + t + 1) * SSTRIDE;
        float ni[8], nj[8];
        load8(ni, rown + i0);
        load8(nj, rown + j0);

        float d[8];
#pragma unroll
        for (int k = 0; k < 8; k++) d[k] = nj[k] - cj[k];
        u64 d2[4];
#pragma unroll
        for (int q = 0; q < 4; q++) d2[q] = pk2(d[2*q], d[2*q+1]);
        if (!FULL) {
            u64 m = (u64)0 - (u64)(l0l + t < hi);   // all-ones if valid
#pragma unroll
            for (int q = 0; q < 4; q++) d2[q] &= m;
        }
        u64 sd[8];
#pragma unroll
        for (int a = 0; a < 8; a++) {
            float s = ci[a] + ni[a];
            sd[a] = pk2(s, s);
        }
#pragma unroll
        for (int a = 0; a < 8; a++)
#pragma unroll
            for (int q = 0; q < 4; q++)
                acc[a][q] = fma2(sd[a], d2[q], acc[a][q]);
#pragma unroll
        for (int k = 0; k < 8; k++) { ci[k] = ni[k]; cj[k] = nj[k]; }
    }
}

__global__ __launch_bounds__(NTHREADS, 3)
void logsig_main(const float* __restrict__ x, float* __restrict__ out)
{
    __shared__ __align__(16) float sbuf[2][SROWS * SSTRIDE];
    __shared__ float sx0[DIM];
    __shared__ float sxL[DIM];

    const int b    = blockIdx.x >> 2;
    const int sub  = blockIdx.x & 3;        // {half, tileset}
    const int half = sub >> 1;
    const int ts   = sub & 1;
    const int tid  = threadIdx.x;
    const int wid  = tid >> 5;
    const int lane = tid & 31;

    const float* __restrict__ xb = x + (size_t)b * (LSEQ * DIM);

    if (tid < DIM)            sx0[tid]       = xb[tid];
    else if (tid < 2 * DIM)   sxL[tid - DIM] = xb[(size_t)(LSEQ - 1) * DIM + (tid - DIM)];

    const int lo = half * HALFL;
    const int hi = (half == 0) ? HALFL : (LSEQ - 1);

    const int tile = ts * NWARPS + wid;
    const int i0 = c_i0[tile];
    const int j0 = c_j0[tile];

    u64 acc[8][4];
#pragma unroll
    for (int a = 0; a < 8; a++)
#pragma unroll
        for (int q = 0; q < 4; q++) acc[a][q] = 0ull;

    // stage chunk 0 (zero-fill rows past the sequence end)
    {
        const int base = lo;
        for (int e = tid; e < SROWS * 8; e += NTHREADS) {
            int r  = e >> 3;
            int c4 = (e & 7) << 2;
            int gr = base + r;
            float4 v = make_float4(0.f, 0.f, 0.f, 0.f);
            if (gr < LSEQ)
                v = *reinterpret_cast<const float4*>(xb + (size_t)gr * DIM + c4);
            *reinterpret_cast<float4*>(&sbuf[0][r * SSTRIDE + c4]) = v;
        }
    }
    __syncthreads();

    for (int c = 0; c < NCHUNK; c++) {
        // prefetch next chunk into the other buffer (overlaps with compute below)
        if (c + 1 < NCHUNK) {
            const int base = lo + (c + 1) * CHUNK;
            float* dst = sbuf[(c + 1) & 1];
            for (int e = tid; e < SROWS * 8; e += NTHREADS) {
                int r  = e >> 3;
                int c4 = (e & 7) << 2;
                int gr = base + r;
                float4 v = make_float4(0.f, 0.f, 0.f, 0.f);
                if (gr < LSEQ)
                    v = *reinterpret_cast<const float4*>(xb + (size_t)gr * DIM + c4);
                *reinterpret_cast<float4*>(&dst[r * SSTRIDE + c4]) = v;
            }
        }

        const float* buf = sbuf[c & 1];
        const int r0  = lane * CL;
        const int l0l = lo + c * CHUNK + lane * CL;

        if (c < NCHUNK - 1)
            chunk_compute<true >(buf, r0, l0l, hi, i0, j0, acc);
        else
            chunk_compute<false>(buf, r0, l0l, hi, i0, j0, acc);

        __syncthreads();
    }

    // warp-level butterfly reduction over the 32 l-slices
#pragma unroll
    for (int a = 0; a < 8; a++)
#pragma unroll
        for (int q = 0; q < 4; q++) {
            u64 v = acc[a][q];
#pragma unroll
            for (int off = 16; off > 0; off >>= 1)
                v = add2(v, __shfl_xor_sync(0xFFFFFFFFu, v, off));
            acc[a][q] = v;
        }

    float* outb = out + (size_t)b * OUTD;

    // level-1 terms (exactly one block per batch writes them; out is pre-zeroed)
    if (sub == 0 && wid == 0) outb[lane] = sxL[lane] - sx0[lane];

    // areas: each lane writes 2 of the 64 tile entries (upper-triangle only)
#pragma unroll
    for (int e2 = 0; e2 < 2; e2++) {
        int e  = lane + 32 * e2;
        int a  = e >> 3;
        int bb = e & 7;
        int i  = i0 + a;
        int j  = j0 + bb;
        if (j > i) {
            float v0, v1; upk2(acc[a][bb >> 1], v0, v1);
            float C   = (bb & 1) ? v1 : v0;
            float val = 0.5f * C;
            if (half == 0) {
                // telescope + x0 corrections, applied exactly once per (i,j)
                float x0i = sx0[i];
                float li  = sxL[i] - x0i;
                float lj  = sxL[j] - sx0[j];
                val -= x0i * lj + 0.5f * li * lj;
            }
            int idx = DIM + i * (2 * DIM - 1 - i) / 2 + (j - i - 1);
            atomicAdd(&outb[idx], val);
        }
    }
}

extern "C" void kernel_launch(void* const* d_in, const int* in_sizes, int n_in,
                              void* d_out, int out_size)
{
    const float* x = (const float*)d_in[0];
    float* out = (float*)d_out;
    const int B = in_sizes[0] / (LSEQ * DIM);

    zero_out_kernel<<<(out_size + 255) / 256, 256>>>(out, out_size);
    logsig_main<<<4 * B, NTHREADS>>>(x, out);
}

// round 8
// speedup vs baseline: 3.6438x; 1.1654x over previous
#include <cuda_runtime.h>
#include <cstdint>

typedef unsigned long long u64;
typedef unsigned int u32;

#define LSEQ    2048
#define DIM     32
#define CL      5             // consecutive l's per lane (odd -> conflict-free with stride 36)
#define CHUNK   160           // CL * 32
#define SROWS   161           // CHUNK + 1 boundary row
#define SSTRIDE 36            // floats per row in smem (16B aligned, bank shift 4/row)
#define NTILES  10
#define NWARPS  5             // warps per block (one tileset = 5 tiles)
#define NTHREADS 160
#define HALFL   1024
#define NCHUNK  7             // ceil(1024/160)
#define OUTD    528
#define SIGN2   0x8000000080000000ULL

__constant__ int c_i0[NTILES] = {0,0,0,0,8, 8,8,16,16,24};
__constant__ int c_j0[NTILES] = {0,8,16,24,8, 16,24,16,24,24};

__device__ __forceinline__ u64 pk2(float lo, float hi) {
    u64 r; asm("mov.b64 %0, {%1, %2};" : "=l"(r) : "f"(lo), "f"(hi)); return r;
}
__device__ __forceinline__ void upk2(u64 v, float& a, float& b) {
    asm("mov.b64 {%0, %1}, %2;" : "=f"(a), "=f"(b) : "l"(v));
}
__device__ __forceinline__ u64 fma2(u64 a, u64 b, u64 c) {
    u64 r; asm("fma.rn.f32x2 %0, %1, %2, %3;" : "=l"(r) : "l"(a), "l"(b), "l"(c)); return r;
}
__device__ __forceinline__ u64 add2(u64 a, u64 b) {
    u64 r; asm("add.rn.f32x2 %0, %1, %2;" : "=l"(r) : "l"(a), "l"(b)); return r;
}

__device__ __forceinline__ void load8(float (&v)[8], const float* p) {
    float4 a = *reinterpret_cast<const float4*>(p);
    float4 b = *reinterpret_cast<const float4*>(p + 4);
    v[0]=a.x; v[1]=a.y; v[2]=a.z; v[3]=a.w;
    v[4]=b.x; v[5]=b.y; v[6]=b.z; v[7]=b.w;
}
__device__ __forceinline__ void load4p(u64 (&v)[4], const float* p) {
    ulonglong2 a = *reinterpret_cast<const ulonglong2*>(p);
    ulonglong2 b = *reinterpret_cast<const ulonglong2*>(p + 4);
    v[0]=a.x; v[1]=a.y; v[2]=b.x; v[3]=b.y;
}

__device__ __forceinline__ void cp16(u32 s_addr, const float* g, u32 szr) {
    asm volatile("cp.async.cg.shared.global [%0], [%1], 16, %2;"
                 :: "r"(s_addr), "l"(g), "r"(szr));
}
__device__ __forceinline__ void cp_commit() { asm volatile("cp.async.commit_group;"); }
__device__ __forceinline__ void cp_wait0()  { asm volatile("cp.async.wait_group 0;" ::: "memory"); }

__global__ void zero_out_kernel(float* __restrict__ out, int n) {
    int i = blockIdx.x * blockDim.x + threadIdx.x;
    if (i < n) out[i] = 0.0f;
}

// Stage one chunk (SROWS rows) into smem via cp.async; zero-fill rows past LSEQ.
__device__ __forceinline__ void stage_chunk(
    const float* __restrict__ xb, int base, float* dst, int tid)
{
    u32 dbase = (u32)__cvta_generic_to_shared(dst);
#pragma unroll
    for (int it = 0; it < 9; it++) {
        int e = tid + it * NTHREADS;
        if (e < SROWS * 8) {
            int r  = e >> 3;
            int c4 = (e & 7) << 2;
            int gr = base + r;
            u32 sz  = (gr < LSEQ) ? 16u : 0u;
            int grc = (gr < LSEQ) ? gr : (LSEQ - 1);
            cp16(dbase + (u32)(r * SSTRIDE + c4) * 4u,
                 xb + (size_t)grc * DIM + c4, sz);
        }
    }
    cp_commit();
}

// Inner chunk compute. FULL=true -> every l in range (no masking needed).
template<bool FULL>
__device__ __forceinline__ void chunk_compute(
    const float* __restrict__ buf, int r0, int l0l, int hi,
    int i0, int j0, u64 (&acc)[8][4])
{
    const float* rowc = buf + r0 * SSTRIDE;
    float ci[8];
    u64   cj2[4];
    load8 (ci,  rowc + i0);
    load4p(cj2, rowc + j0);

#pragma unroll
    for (int t = 0; t < CL; t++) {
        const float* rown = buf + (r0 + t + 1) * SSTRIDE;
        float ni[8];
        u64   nj2[4];
        load8 (ni,  rown + i0);
        load4p(nj2, rown + j0);

        // d pairs along j: nj - cj via packed add with sign-flipped cj
        u64 d2[4];
#pragma unroll
        for (int q = 0; q < 4; q++) d2[q] = add2(nj2[q], cj2[q] ^ SIGN2);
        if (!FULL) {
            u64 m = (u64)0 - (u64)(l0l + t < hi);   // all-ones if valid
#pragma unroll
            for (int q = 0; q < 4; q++) d2[q] &= m;
        }
        // s duplicated along i
        u64 sd[8];
#pragma unroll
        for (int a = 0; a < 8; a++) {
            float s = ci[a] + ni[a];
            sd[a] = pk2(s, s);
        }
#pragma unroll
        for (int a = 0; a < 8; a++)
#pragma unroll
            for (int q = 0; q < 4; q++)
                acc[a][q] = fma2(sd[a], d2[q], acc[a][q]);
#pragma unroll
        for (int k = 0; k < 8; k++) ci[k] = ni[k];
#pragma unroll
        for (int q = 0; q < 4; q++) cj2[q] = nj2[q];
    }
}

__global__ __launch_bounds__(NTHREADS, 3)
void logsig_main(const float* __restrict__ x, float* __restrict__ out)
{
    __shared__ __align__(16) float sbuf[2][SROWS * SSTRIDE];
    __shared__ float sx0[DIM];
    __shared__ float sxL[DIM];

    const int b    = blockIdx.x >> 2;
    const int sub  = blockIdx.x & 3;        // {half, tileset}
    const int half = sub >> 1;
    const int ts   = sub & 1;
    const int tid  = threadIdx.x;
    const int wid  = tid >> 5;
    const int lane = tid & 31;

    const float* __restrict__ xb = x + (size_t)b * (LSEQ * DIM);

    if (tid < DIM)            sx0[tid]       = xb[tid];
    else if (tid < 2 * DIM)   sxL[tid - DIM] = xb[(size_t)(LSEQ - 1) * DIM + (tid - DIM)];

    const int lo = half * HALFL;
    const int hi = (half == 0) ? HALFL : (LSEQ - 1);

    const int tile = ts * NWARPS + wid;
    const int i0 = c_i0[tile];
    const int j0 = c_j0[tile];

    u64 acc[8][4];
#pragma unroll
    for (int a = 0; a < 8; a++)
#pragma unroll
        for (int q = 0; q < 4; q++) acc[a][q] = 0ull;

    // stage chunk 0
    stage_chunk(xb, lo, sbuf[0], tid);
    cp_wait0();
    __syncthreads();

    for (int c = 0; c < NCHUNK; c++) {
        // async-prefetch next chunk into the other buffer (no register landing, no stall)
        if (c + 1 < NCHUNK)
            stage_chunk(xb, lo + (c + 1) * CHUNK, sbuf[(c + 1) & 1], tid);

        const float* buf = sbuf[c & 1];
        const int r0  = lane * CL;
        const int l0l = lo + c * CHUNK + lane * CL;

        if (c < NCHUNK - 1)
            chunk_compute<true >(buf, r0, l0l, hi, i0, j0, acc);
        else
            chunk_compute<false>(buf, r0, l0l, hi, i0, j0, acc);

        cp_wait0();          // prefetch has had the whole compute phase to land
        __syncthreads();
    }

    // warp-level butterfly reduction over the 32 l-slices
#pragma unroll
    for (int a = 0; a < 8; a++)
#pragma unroll
        for (int q = 0; q < 4; q++) {
            u64 v = acc[a][q];
#pragma unroll
            for (int off = 16; off > 0; off >>= 1)
                v = add2(v, __shfl_xor_sync(0xFFFFFFFFu, v, off));
            acc[a][q] = v;
        }

    float* outb = out + (size_t)b * OUTD;

    // level-1 terms (exactly one block per batch writes them; out is pre-zeroed)
    if (sub == 0 && wid == 0) outb[lane] = sxL[lane] - sx0[lane];

    // areas: each lane writes 2 of the 64 tile entries (upper-triangle only)
#pragma unroll
    for (int e2 = 0; e2 < 2; e2++) {
        int e  = lane + 32 * e2;
        int a  = e >> 3;
        int bb = e & 7;
        int i  = i0 + a;
        int j  = j0 + bb;
        if (j > i) {
            float v0, v1; upk2(acc[a][bb >> 1], v0, v1);
            float C   = (bb & 1) ? v1 : v0;
            float val = 0.5f * C;
            if (half == 0) {
                // telescope + x0 corrections, applied exactly once per (i,j)
                float x0i = sx0[i];
                float li  = sxL[i] - x0i;
                float lj  = sxL[j] - sx0[j];
                val -= x0i * lj + 0.5f * li * lj;
            }
            int idx = DIM + i * (2 * DIM - 1 - i) / 2 + (j - i - 1);
            atomicAdd(&outb[idx], val);
        }
    }
}

extern "C" void kernel_launch(void* const* d_in, const int* in_sizes, int n_in,
                              void* d_out, int out_size)
{
    const float* x = (const float*)d_in[0];
    float* out = (float*)d_out;
    const int B = in_sizes[0] / (LSEQ * DIM);

    zero_out_kernel<<<(out_size + 255) / 256, 256>>>(out, out_size);
    logsig_main<<<4 * B, NTHREADS>>>(x, out);
}

// round 9
// speedup vs baseline: 4.3032x; 1.1810x over previous
#include <cuda_runtime.h>
#include <cstdint>

typedef unsigned long long u64;
typedef unsigned int u32;

#define LSEQ    2048
#define DIM     32
#define CL      5             // consecutive l's per lane (odd -> conflict-free with stride 36)
#define CHUNK   160           // CL * 32
#define SROWS   161           // CHUNK + 1 boundary row
#define SSTRIDE 36            // floats per row in smem (16B aligned, bank shift 4/row)
#define NTILES  10
#define NWARPS  5             // warps per block (one tileset = 5 tiles)
#define NTHREADS 160
#define HALFL   1024
#define NCHUNK  7             // ceil(1024/160)
#define OUTD    528

__constant__ int c_i0[NTILES] = {0,0,0,0,8, 8,8,16,16,24};
__constant__ int c_j0[NTILES] = {0,8,16,24,8, 16,24,16,24,24};

__device__ __forceinline__ u64 pk2(float lo, float hi) {
    u64 r; asm("mov.b64 %0, {%1, %2};" : "=l"(r) : "f"(lo), "f"(hi)); return r;
}
__device__ __forceinline__ void upk2(u64 v, float& a, float& b) {
    asm("mov.b64 {%0, %1}, %2;" : "=f"(a), "=f"(b) : "l"(v));
}
__device__ __forceinline__ u64 fma2(u64 a, u64 b, u64 c) {
    u64 r; asm("fma.rn.f32x2 %0, %1, %2, %3;" : "=l"(r) : "l"(a), "l"(b), "l"(c)); return r;
}
__device__ __forceinline__ u64 add2(u64 a, u64 b) {
    u64 r; asm("add.rn.f32x2 %0, %1, %2;" : "=l"(r) : "l"(a), "l"(b)); return r;
}
__device__ __forceinline__ u64 swp(u64 v) {      // (a,b) -> (b,a): 2 MOV
    u32 a, b; asm("mov.b64 {%0, %1}, %2;" : "=r"(a), "=r"(b) : "l"(v));
    u64 r;    asm("mov.b64 %0, {%1, %2};" : "=l"(r) : "r"(b), "r"(a));
    return r;
}

__device__ __forceinline__ void load4p(u64 (&v)[4], const float* p) {
    ulonglong2 a = *reinterpret_cast<const ulonglong2*>(p);
    ulonglong2 b = *reinterpret_cast<const ulonglong2*>(p + 4);
    v[0]=a.x; v[1]=a.y; v[2]=b.x; v[3]=b.y;
}

__device__ __forceinline__ void cp16(u32 s_addr, const float* g, u32 szr) {
    asm volatile("cp.async.cg.shared.global [%0], [%1], 16, %2;"
                 :: "r"(s_addr), "l"(g), "r"(szr));
}
__device__ __forceinline__ void cp_commit() { asm volatile("cp.async.commit_group;"); }
__device__ __forceinline__ void cp_wait0()  { asm volatile("cp.async.wait_group 0;" ::: "memory"); }

__global__ void zero_out_kernel(float* __restrict__ out, int n) {
    int i = blockIdx.x * blockDim.x + threadIdx.x;
    if (i < n) out[i] = 0.0f;
}

// Stage one chunk (SROWS rows) into smem via cp.async; zero-fill rows past LSEQ.
__device__ __forceinline__ void stage_chunk(
    const float* __restrict__ xb, int base, float* dst, int tid)
{
    u32 dbase = (u32)__cvta_generic_to_shared(dst);
#pragma unroll
    for (int it = 0; it < 9; it++) {
        int e = tid + it * NTHREADS;
        if (e < SROWS * 8) {
            int r  = e >> 3;
            int c4 = (e & 7) << 2;
            int gr = base + r;
            u32 sz  = (gr < LSEQ) ? 16u : 0u;
            int grc = (gr < LSEQ) ? gr : (LSEQ - 1);
            cp16(dbase + (u32)(r * SSTRIDE + c4) * 4u,
                 xb + (size_t)grc * DIM + c4, sz);
        }
    }
    cp_commit();
}

// Inner chunk compute with parity-pair accumulation.
// aee[p][q]: (s[2p]d[2q], s[2p+1]d[2q+1]) -> entries (2p,2q) & (2p+1,2q+1)
// aeo[p][q]: (s[2p+1]d[2q], s[2p]d[2q+1]) -> entries (2p+1,2q) & (2p,2q+1)
// DIAG: i0==j0, single slice, upper-triangle pairs only.
template<bool DIAG, bool FULL>
__device__ __forceinline__ void chunk_compute(
    const float* __restrict__ buf, int r0, int l0l, int hi,
    int i0, int j0, u64 (&aee)[4][4], u64 (&aeo)[4][4], u64 m1)
{
    const float* rowc = buf + r0 * SSTRIDE;
    u64 ci2[4], cj2[4];
    load4p(ci2, rowc + i0);
    if (!DIAG) load4p(cj2, rowc + j0);

#pragma unroll
    for (int t = 0; t < CL; t++) {
        const float* rown = buf + (r0 + t + 1) * SSTRIDE;
        u64 ni2[4], nj2[4];
        load4p(ni2, rown + i0);
        if (!DIAG) load4p(nj2, rown + j0);

        // d = nj - cj   (as fma2 with (-1,-1) multiplier; DIAG uses the i slice)
        u64 d2[4];
#pragma unroll
        for (int q = 0; q < 4; q++)
            d2[q] = fma2(DIAG ? ci2[q] : cj2[q], m1, DIAG ? ni2[q] : nj2[q]);
        if (!FULL) {
            u64 m = (u64)0 - (u64)(l0l + t < hi);   // all-ones if valid
#pragma unroll
            for (int q = 0; q < 4; q++) d2[q] &= m;
        }
        // s = ci + ni, naturally packed; swapped copy for the odd parity bank
        u64 s2[4], sw[4];
#pragma unroll
        for (int p = 0; p < 4; p++) { s2[p] = add2(ci2[p], ni2[p]); sw[p] = swp(s2[p]); }

#pragma unroll
        for (int p = 0; p < 4; p++)
#pragma unroll
            for (int q = 0; q < 4; q++) {
                if (!DIAG || q > p)  aee[p][q] = fma2(s2[p], d2[q], aee[p][q]);
                if (!DIAG || q >= p) aeo[p][q] = fma2(sw[p], d2[q], aeo[p][q]);
            }
#pragma unroll
        for (int k = 0; k < 4; k++) ci2[k] = ni2[k];
        if (!DIAG) {
#pragma unroll
            for (int k = 0; k < 4; k++) cj2[k] = nj2[k];
        }
    }
}

__global__ __launch_bounds__(NTHREADS, 3)
void logsig_main(const float* __restrict__ x, float* __restrict__ out)
{
    __shared__ __align__(16) float sbuf[2][SROWS * SSTRIDE];
    __shared__ float sx0[DIM];
    __shared__ float sxL[DIM];

    const int b    = blockIdx.x >> 2;
    const int sub  = blockIdx.x & 3;        // {half, tileset}
    const int half = sub >> 1;
    const int ts   = sub & 1;
    const int tid  = threadIdx.x;
    const int wid  = tid >> 5;
    const int lane = tid & 31;

    const float* __restrict__ xb = x + (size_t)b * (LSEQ * DIM);

    if (tid < DIM)            sx0[tid]       = xb[tid];
    else if (tid < 2 * DIM)   sxL[tid - DIM] = xb[(size_t)(LSEQ - 1) * DIM + (tid - DIM)];

    const int lo = half * HALFL;
    const int hi = (half == 0) ? HALFL : (LSEQ - 1);

    const int tile = ts * NWARPS + wid;
    const int i0 = c_i0[tile];
    const int j0 = c_j0[tile];
    const bool diag = (i0 == j0);
    const u64 m1 = pk2(-1.0f, -1.0f);

    u64 aee[4][4], aeo[4][4];
#pragma unroll
    for (int p = 0; p < 4; p++)
#pragma unroll
        for (int q = 0; q < 4; q++) { aee[p][q] = 0ull; aeo[p][q] = 0ull; }

    // stage chunk 0
    stage_chunk(xb, lo, sbuf[0], tid);
    cp_wait0();
    __syncthreads();

    for (int c = 0; c < NCHUNK; c++) {
        if (c + 1 < NCHUNK)
            stage_chunk(xb, lo + (c + 1) * CHUNK, sbuf[(c + 1) & 1], tid);

        const float* buf = sbuf[c & 1];
        const int r0  = lane * CL;
        const int l0l = lo + c * CHUNK + lane * CL;

        if (c < NCHUNK - 1) {
            if (diag) chunk_compute<true , true >(buf, r0, l0l, hi, i0, j0, aee, aeo, m1);
            else      chunk_compute<false, true >(buf, r0, l0l, hi, i0, j0, aee, aeo, m1);
        } else {
            if (diag) chunk_compute<true , false>(buf, r0, l0l, hi, i0, j0, aee, aeo, m1);
            else      chunk_compute<false, false>(buf, r0, l0l, hi, i0, j0, aee, aeo, m1);
        }

        cp_wait0();          // prefetch has had the whole compute phase to land
        __syncthreads();
    }

    // warp-level butterfly reduction over the 32 l-slices
#pragma unroll
    for (int p = 0; p < 4; p++)
#pragma unroll
        for (int q = 0; q < 4; q++) {
            u64 v = aee[p][q];
#pragma unroll
            for (int off = 16; off > 0; off >>= 1)
                v = add2(v, __shfl_xor_sync(0xFFFFFFFFu, v, off));
            aee[p][q] = v;
            u64 w = aeo[p][q];
#pragma unroll
            for (int off = 16; off > 0; off >>= 1)
                w = add2(w, __shfl_xor_sync(0xFFFFFFFFu, w, off));
            aeo[p][q] = w;
        }

    float* outb = out + (size_t)b * OUTD;

    // level-1 terms (exactly one block per batch writes them; out is pre-zeroed)
    if (sub == 0 && wid == 0) outb[lane] = sxL[lane] - sx0[lane];

    // areas writeout: e = {bank, p, q, h}
#pragma unroll
    for (int e2 = 0; e2 < 2; e2++) {
        int e    = lane + 32 * e2;
        int bank = e >> 5;
        int p    = (e >> 3) & 3;
        int q    = (e >> 1) & 3;
        int h    = e & 1;
        int i, j;
        if (bank == 0) { i = i0 + 2 * p + h;       j = j0 + 2 * q + h; }
        else           { i = i0 + 2 * p + (1 - h); j = j0 + 2 * q + h; }
        if (j > i) {
            float v0, v1;
            upk2(bank == 0 ? aee[p][q] : aeo[p][q], v0, v1);
            float C   = h ? v1 : v0;
            float val = 0.5f * C;
            if (half == 0) {
                // telescope + x0 corrections, applied exactly once per (i,j)
                float x0i = sx0[i];
                float li  = sxL[i] - x0i;
                float lj  = sxL[j] - sx0[j];
                val -= x0i * lj + 0.5f * li * lj;
            }
            int idx = DIM + i * (2 * DIM - 1 - i) / 2 + (j - i - 1);
            atomicAdd(&outb[idx], val);
        }
    }
}

extern "C" void kernel_launch(void* const* d_in, const int* in_sizes, int n_in,
                              void* d_out, int out_size)
{
    const float* x = (const float*)d_in[0];
    float* out = (float*)d_out;
    const int B = in_sizes[0] / (LSEQ * DIM);

    zero_out_kernel<<<(out_size + 255) / 256, 256>>>(out, out_size);
    logsig_main<<<4 * B, NTHREADS>>>(x, out);
}

// round 12
// speedup vs baseline: 4.4714x; 1.0391x over previous
#include <cuda_runtime.h>
#include <cuda.h>
#include <cstdint>

typedef unsigned long long u64;
typedef unsigned int u32;

#define LSEQ    2048
#define DIM     32
#define CL      5             // consecutive rows per lane (5 coprime 8 -> conflict-free under SW128)
#define CHUNK   160           // CL * 32
#define SROWS   161           // CHUNK + 1 boundary row
#define ROWB    128           // bytes per row in smem (natural, TMA SW128)
#define TXB     (SROWS * ROWB)   // 20608 bytes per TMA box
#define BUFB    21504         // buffer padded to 1024B multiple
#define NTILES  10
#define NWARPS  5
#define NTHREADS 160
#define HALFL   1024
#define NCHUNK  7
#define OUTD    528

__constant__ int c_i0[NTILES] = {0,0,0,0,8, 8,8,16,16,24};
__constant__ int c_j0[NTILES] = {0,8,16,24,8, 16,24,16,24,24};

__device__ __forceinline__ u64 pk2(float lo, float hi) {
    u64 r; asm("mov.b64 %0, {%1, %2};" : "=l"(r) : "f"(lo), "f"(hi)); return r;
}
__device__ __forceinline__ void upk2(u64 v, float& a, float& b) {
    asm("mov.b64 {%0, %1}, %2;" : "=f"(a), "=f"(b) : "l"(v));
}
__device__ __forceinline__ u64 fma2(u64 a, u64 b, u64 c) {
    u64 r; asm("fma.rn.f32x2 %0, %1, %2, %3;" : "=l"(r) : "l"(a), "l"(b), "l"(c)); return r;
}
__device__ __forceinline__ u64 add2(u64 a, u64 b) {
    u64 r; asm("add.rn.f32x2 %0, %1, %2;" : "=l"(r) : "l"(a), "l"(b)); return r;
}
__device__ __forceinline__ u64 swp(u64 v) {
    u32 a, b; asm("mov.b64 {%0, %1}, %2;" : "=r"(a), "=r"(b) : "l"(v));
    u64 r;    asm("mov.b64 %0, {%1, %2};" : "=l"(r) : "r"(b), "r"(a));
    return r;
}

__device__ __forceinline__ void mbar_init(u32 a, u32 cnt) {
    asm volatile("mbarrier.init.shared.b64 [%0], %1;" :: "r"(a), "r"(cnt) : "memory");
}
__device__ __forceinline__ void mbar_expect(u32 a, u32 tx) {
    asm volatile("mbarrier.arrive.expect_tx.shared.b64 _, [%0], %1;" :: "r"(a), "r"(tx) : "memory");
}
__device__ __forceinline__ void mbar_wait(u32 a, u32 parity) {
    asm volatile(
        "{\n\t.reg .pred P;\n\t"
        "WL_%=:\n\t"
        "mbarrier.try_wait.parity.acquire.cta.shared::cta.b64 P, [%0], %1, 0x989680;\n\t"
        "@P bra WD_%=;\n\t"
        "bra WL_%=;\n\t"
        "WD_%=:\n\t}"
        :: "r"(a), "r"(parity) : "memory");
}
__device__ __forceinline__ void tma3d(u32 dst, const CUtensorMap* m, int cx, int cy, int cz, u32 mbar) {
    asm volatile(
        "cp.async.bulk.tensor.3d.shared::cta.global.tile.mbarrier::complete_tx::bytes "
        "[%0], [%1, {%2, %3, %4}], [%5];"
        :: "r"(dst), "l"(m), "r"(cx), "r"(cy), "r"(cz), "r"(mbar) : "memory");
}

// load one 8-wide slice (32B) of row r as 4 packed pairs, SW128-aware (two 16B loads)
__device__ __forceinline__ void lds2(u64 (&v)[4], const char* buf, int r, int c0) {
    int sw = (r & 7) << 4;
    ulonglong2 a = *reinterpret_cast<const ulonglong2*>(buf + r * ROWB + (c0 ^ sw));
    ulonglong2 b = *reinterpret_cast<const ulonglong2*>(buf + r * ROWB + ((c0 + 16) ^ sw));
    v[0]=a.x; v[1]=a.y; v[2]=b.x; v[3]=b.y;
}

__global__ void zero_out_kernel(float* __restrict__ out, int n) {
    int i = blockIdx.x * blockDim.x + threadIdx.x;
    if (i < n) out[i] = 0.0f;
}

// Parity-pair accumulation (identical math to the passing R9 kernel).
template<bool DIAG, bool FULL>
__device__ __forceinline__ void chunk_compute(
    const char* __restrict__ buf, int r0, int l0l, int hi,
    int ci0, int cj0, u64 (&aee)[4][4], u64 (&aeo)[4][4], u64 m1)
{
    u64 ci2[4], cj2[4];
    lds2(ci2, buf, r0, ci0);
    if (!DIAG) lds2(cj2, buf, r0, cj0);

#pragma unroll
    for (int t = 0; t < CL; t++) {
        int rn = r0 + t + 1;
        u64 ni2[4], nj2[4];
        lds2(ni2, buf, rn, ci0);
        if (!DIAG) lds2(nj2, buf, rn, cj0);

        u64 d2[4];
#pragma unroll
        for (int q = 0; q < 4; q++)
            d2[q] = fma2(DIAG ? ci2[q] : cj2[q], m1, DIAG ? ni2[q] : nj2[q]);
        if (!FULL) {
            u64 m = (u64)0 - (u64)(l0l + t < hi);
#pragma unroll
            for (int q = 0; q < 4; q++) d2[q] &= m;
        }
        u64 s2[4], sw[4];
#pragma unroll
        for (int p = 0; p < 4; p++) { s2[p] = add2(ci2[p], ni2[p]); sw[p] = swp(s2[p]); }

#pragma unroll
        for (int p = 0; p < 4; p++)
#pragma unroll
            for (int q = 0; q < 4; q++) {
                if (!DIAG || q > p)  aee[p][q] = fma2(s2[p], d2[q], aee[p][q]);
                if (!DIAG || q >= p) aeo[p][q] = fma2(sw[p], d2[q], aeo[p][q]);
            }
#pragma unroll
        for (int k = 0; k < 4; k++) ci2[k] = ni2[k];
        if (!DIAG) {
#pragma unroll
            for (int k = 0; k < 4; k++) cj2[k] = nj2[k];
        }
    }
}

__global__ __launch_bounds__(NTHREADS, 3)
void logsig_main(const __grid_constant__ CUtensorMap tmap,
                 const float* __restrict__ x, float* __restrict__ out)
{
    __shared__ __align__(1024) char sbuf[2][BUFB];
    __shared__ u64 mb[2];
    __shared__ float sx0[DIM];
    __shared__ float sxL[DIM];

    const int b    = blockIdx.x >> 2;
    const int sub  = blockIdx.x & 3;        // {half, tileset}
    const int half = sub >> 1;
    const int ts   = sub & 1;
    const int tid  = threadIdx.x;
    const int wid  = tid >> 5;
    const int lane = tid & 31;

    const float* __restrict__ xb = x + (size_t)b * (LSEQ * DIM);

    if (tid < DIM)            sx0[tid]       = xb[tid];
    else if (tid < 2 * DIM)   sxL[tid - DIM] = xb[(size_t)(LSEQ - 1) * DIM + (tid - DIM)];

    const int lo = half * HALFL;
    const int hi = (half == 0) ? HALFL : (LSEQ - 1);

    const int tile = ts * NWARPS + wid;
    const int i0 = c_i0[tile];
    const int j0 = c_j0[tile];
    const int ci0 = i0 * 4, cj0 = j0 * 4;   // byte offsets within a row
    const bool diag = (i0 == j0);
    const u64 m1 = pk2(-1.0f, -1.0f);

    u32 mbar[2];
    mbar[0] = (u32)__cvta_generic_to_shared(&mb[0]);
    mbar[1] = (u32)__cvta_generic_to_shared(&mb[1]);
    u32 sdst[2];
    sdst[0] = (u32)__cvta_generic_to_shared(&sbuf[0][0]);
    sdst[1] = (u32)__cvta_generic_to_shared(&sbuf[1][0]);

    if (tid == 0) {
        mbar_init(mbar[0], 1);
        mbar_init(mbar[1], 1);
        asm volatile("fence.proxy.async.shared::cta;" ::: "memory");
    }
    __syncthreads();

    u64 aee[4][4], aeo[4][4];
#pragma unroll
    for (int p = 0; p < 4; p++)
#pragma unroll
        for (int q = 0; q < 4; q++) { aee[p][q] = 0ull; aeo[p][q] = 0ull; }

    // issue chunk 0
    if (tid == 0) {
        mbar_expect(mbar[0], TXB);
        tma3d(sdst[0], &tmap, 0, lo, b, mbar[0]);
    }

    for (int c = 0; c < NCHUNK; c++) {
        if (c + 1 < NCHUNK && tid == 0) {
            int bi = (c + 1) & 1;
            mbar_expect(mbar[bi], TXB);
            tma3d(sdst[bi], &tmap, 0, lo + (c + 1) * CHUNK, b, mbar[bi]);
        }

        mbar_wait(mbar[c & 1], (c >> 1) & 1);

        const char* buf = sbuf[c & 1];
        const int r0  = lane * CL;
        const int l0l = lo + c * CHUNK + lane * CL;

        if (c < NCHUNK - 1) {
            if (diag) chunk_compute<true , true >(buf, r0, l0l, hi, ci0, cj0, aee, aeo, m1);
            else      chunk_compute<false, true >(buf, r0, l0l, hi, ci0, cj0, aee, aeo, m1);
        } else {
            if (diag) chunk_compute<true , false>(buf, r0, l0l, hi, ci0, cj0, aee, aeo, m1);
            else      chunk_compute<false, false>(buf, r0, l0l, hi, ci0, cj0, aee, aeo, m1);
        }

        __syncthreads();   // all warps done reading buf before it is re-targeted
    }

    // warp-level butterfly reduction over the 32 l-slices
#pragma unroll
    for (int p = 0; p < 4; p++)
#pragma unroll
        for (int q = 0; q < 4; q++) {
            u64 v = aee[p][q];
#pragma unroll
            for (int off = 16; off > 0; off >>= 1)
                v = add2(v, __shfl_xor_sync(0xFFFFFFFFu, v, off));
            aee[p][q] = v;
            u64 w = aeo[p][q];
#pragma unroll
            for (int off = 16; off > 0; off >>= 1)
                w = add2(w, __shfl_xor_sync(0xFFFFFFFFu, w, off));
            aeo[p][q] = w;
        }

    float* outb = out + (size_t)b * OUTD;

    if (sub == 0 && wid == 0) outb[lane] = sxL[lane] - sx0[lane];

    // areas writeout: e = {bank, p, q, h}
#pragma unroll
    for (int e2 = 0; e2 < 2; e2++) {
        int e    = lane + 32 * e2;
        int bank = e >> 5;
        int p    = (e >> 3) & 3;
        int q    = (e >> 1) & 3;
        int h    = e & 1;
        int i, j;
        if (bank == 0) { i = i0 + 2 * p + h;       j = j0 + 2 * q + h; }
        else           { i = i0 + 2 * p + (1 - h); j = j0 + 2 * q + h; }
        if (j > i) {
            float v0, v1;
            upk2(bank == 0 ? aee[p][q] : aeo[p][q], v0, v1);
            float C   = h ? v1 : v0;
            float val = 0.5f * C;
            if (half == 0) {
                float x0i = sx0[i];
                float li  = sxL[i] - x0i;
                float lj  = sxL[j] - sx0[j];
                val -= x0i * lj + 0.5f * li * lj;
            }
            int idx = DIM + i * (2 * DIM - 1 - i) / 2 + (j - i - 1);
            atomicAdd(&outb[idx], val);
        }
    }
}

typedef CUresult (*EncodeTiledFn)(
    CUtensorMap*, CUtensorMapDataType, cuuint32_t, void*,
    const cuuint64_t*, const cuuint64_t*, const cuuint32_t*, const cuuint32_t*,
    CUtensorMapInterleave, CUtensorMapSwizzle, CUtensorMapL2promotion, CUtensorMapFloatOOBfill);

extern "C" void kernel_launch(void* const* d_in, const int* in_sizes, int n_in,
                              void* d_out, int out_size)
{
    const float* x = (const float*)d_in[0];
    float* out = (float*)d_out;
    const int B = in_sizes[0] / (LSEQ * DIM);

    // Build the TMA descriptor (pure host-CPU work; graph-capture safe)
    void* fp = nullptr;
    cudaDriverEntryPointQueryResult st;
    cudaGetDriverEntryPointByVersion("cuTensorMapEncodeTiled", &fp, 12000,
                                     cudaEnableDefault, &st);
    EncodeTiledFn enc = (EncodeTiledFn)fp;

    CUtensorMap tmap;
    cuuint64_t dims[3]    = {DIM, LSEQ, (cuuint64_t)B};
    cuuint64_t strides[2] = {DIM * 4ull, (cuuint64_t)LSEQ * DIM * 4ull};
    cuuint32_t box[3]     = {DIM, SROWS, 1};
    cuuint32_t es[3]      = {1, 1, 1};
    enc(&tmap, CU_TENSOR_MAP_DATA_TYPE_FLOAT32, 3, (void*)x,
        dims, strides, box, es,
        CU_TENSOR_MAP_INTERLEAVE_NONE, CU_TENSOR_MAP_SWIZZLE_128B,
        CU_TENSOR_MAP_L2_PROMOTION_L2_128B, CU_TENSOR_MAP_FLOAT_OOB_FILL_NONE);

    zero_out_kernel<<<(out_size + 255) / 256, 256>>>(out, out_size);
    logsig_main<<<4 * B, NTHREADS>>>(tmap, x, out);
}